// round 1
// baseline (speedup 1.0000x reference)
#include <cuda_runtime.h>
#include <math.h>

// ---------------- constants ----------------
#define HH    64
#define WW    192
#define HW    12288        // 64*192
#define WP    194          // padded width
#define PP    12804        // 66*194
#define CIN   256
#define COUT  128

// ---------------- scratch (device globals; allocation-free) ----------------
__device__ float g_xpad[CIN * PP];      // zero-padded input, flat per channel
__device__ float g_y1[CIN * HW];        // deformable-gather output
__device__ float g_bufP[COUT * HW];     // pointwise outputs (pre-BN)
__device__ float g_bufD[COUT * HW];     // depthwise outputs
__device__ float g_ss[3 * COUT * 2];    // per-stage fused (scale, shift)

// ---------------- pad kernel: x -> g_xpad ----------------
__global__ __launch_bounds__(256) void pad_kernel(const float* __restrict__ x) {
    int t = blockIdx.x * 256 + threadIdx.x;       // over CIN*PP = 3,277,824 (exact multiple)
    int c = t / PP;
    int r = (t % PP) / WP;
    int col = t % WP;
    float v = 0.0f;
    if (r >= 1 && r <= HH && col >= 1 && col <= WW)
        v = x[(c * HH + (r - 1)) * WW + (col - 1)];
    g_xpad[t] = v;
}

// ---------------- deformable gather ----------------
// grid (H=64, 8 channel-groups), block 192 (one pixel per thread)
__global__ __launch_bounds__(192) void gather_kernel(const float* __restrict__ xr,
                                                     const float* __restrict__ rout) {
    const int i = blockIdx.x;
    const int cg = blockIdx.y;
    const int j = threadIdx.x;

    // tap tables: only x_off != 0 taps contribute (orig tap ids 0,2,3,5,6,8)
    const int TT[6] = {0, 2, 3, 5, 6, 8};
    const int XO[6] = {-1, 1, -1, 1, -1, 1};
    const int YO[6] = {-1, -1, 0, 0, 1, 1};

    float w[6][4];
    int   id[6][4];

    {
        float xv = xr[i * WW + j];
        float sig = 1.0f / (1.0f + expf(-xv));
        float o = __fmul_rn(3.0f, sig);
        float v = (float)((i + 1) * WP + (j + 1));
        #pragma unroll
        for (int tt = 0; tt < 6; tt++) {
            float fxo = (float)XO[tt];
            float fyW = (float)(YO[tt] * WP);
            // match JAX's unfused fp32 ops exactly (floor/ceil boundary sensitivity)
            float offv  = __fadd_rn(__fmul_rn(o, fxo), fyW);
            float pre   = __fadd_rn(__fadd_rn(v, fxo), fyW);
            float after = __fadd_rn(pre, offv);
            float avf  = fminf(fmaxf(__fadd_rn(pre, floorf(offv)), 0.0f), (float)(PP - 1));
            float avf1 = fminf(fmaxf(__fadd_rn(avf, fxo), 0.0f), (float)(PP - 1));
            float avc  = fminf(fmaxf(__fadd_rn(pre, ceilf(offv)), 0.0f), (float)(PP - 1));
            float avc1 = fminf(fmaxf(__fadd_rn(avc, fxo), 0.0f), (float)(PP - 1));
            float a  = fabsf(__fadd_rn(after, -avf));
            float b  = fabsf(__fadd_rn(avf1, -after));
            float cc = fabsf(__fadd_rn(after, -avc1));
            float d  = fabsf(__fadd_rn(avc, -after));
            float A1 = fabsf(__fdiv_rn(__fadd_rn(after, -avf), (float)WP));
            float A2 = fabsf(__fdiv_rn(__fadd_rn(avc1, -after), (float)WP));
            w[tt][0] = A1 * a;  id[tt][0] = (int)avf;
            w[tt][1] = A1 * b;  id[tt][1] = (int)avf1;
            w[tt][2] = A2 * cc; id[tt][2] = (int)avc1;
            w[tt][3] = A2 * d;  id[tt][3] = (int)avc;
        }
    }

    const int p = i * WW + j;
    const int c0 = cg * 32;
    for (int cc = 0; cc < 32; cc++) {
        int c = c0 + cc;
        const float* xp = g_xpad + c * PP;
        float acc = 0.0f;
        #pragma unroll
        for (int tt = 0; tt < 6; tt++) {
            float tv = w[tt][0] * __ldg(xp + id[tt][0])
                     + w[tt][1] * __ldg(xp + id[tt][1])
                     + w[tt][2] * __ldg(xp + id[tt][2])
                     + w[tt][3] * __ldg(xp + id[tt][3]);
            acc = fmaf(__ldg(rout + c * 9 + TT[tt]), tv, acc);
        }
        g_y1[c * HW + p] = acc;
    }
}

// ---------------- SGEMM: C[128][12288] = A[128][K] * B[K][12288] ----------------
// tile: BM=128, BN=64, BK=16; 256 threads; 8x4 microtile
template <int K, bool FROM_Y1>
__global__ __launch_bounds__(256) void sgemm_kernel(const float* __restrict__ A) {
    const float* __restrict__ B = FROM_Y1 ? g_y1 : g_bufD;
    float* __restrict__ C = g_bufP;

    __shared__ float As[16][128];
    __shared__ float Bs[16][64];

    const int tid = threadIdx.x;
    const int n0 = blockIdx.x * 64;
    const int tx = tid & 15;
    const int ty = tid >> 4;

    float acc[8][4];
    #pragma unroll
    for (int i = 0; i < 8; i++)
        #pragma unroll
        for (int jj = 0; jj < 4; jj++) acc[i][jj] = 0.0f;

    const int am = tid >> 1;
    const int ak = (tid & 1) * 8;
    const int bk = tid >> 4;
    const int bn = (tid & 15) * 4;

    for (int k0 = 0; k0 < K; k0 += 16) {
        float4 a0 = *(const float4*)(A + am * K + k0 + ak);
        float4 a1 = *(const float4*)(A + am * K + k0 + ak + 4);
        As[ak + 0][am] = a0.x; As[ak + 1][am] = a0.y;
        As[ak + 2][am] = a0.z; As[ak + 3][am] = a0.w;
        As[ak + 4][am] = a1.x; As[ak + 5][am] = a1.y;
        As[ak + 6][am] = a1.z; As[ak + 7][am] = a1.w;
        float4 bv = *(const float4*)(B + (k0 + bk) * HW + n0 + bn);
        *(float4*)&Bs[bk][bn] = bv;
        __syncthreads();
        #pragma unroll
        for (int k = 0; k < 16; k++) {
            float ar[8], br[4];
            *(float4*)(ar)     = *(const float4*)&As[k][ty * 8];
            *(float4*)(ar + 4) = *(const float4*)&As[k][ty * 8 + 4];
            *(float4*)(br)     = *(const float4*)&Bs[k][tx * 4];
            #pragma unroll
            for (int i = 0; i < 8; i++)
                #pragma unroll
                for (int jj = 0; jj < 4; jj++)
                    acc[i][jj] = fmaf(ar[i], br[jj], acc[i][jj]);
        }
        __syncthreads();
    }

    const int row = ty * 8;
    #pragma unroll
    for (int i = 0; i < 8; i++) {
        float4 o;
        o.x = acc[i][0]; o.y = acc[i][1]; o.z = acc[i][2]; o.w = acc[i][3];
        *(float4*)(C + (row + i) * HW + n0 + tx * 4) = o;
    }
}

// ---------------- BN stats: per-channel sum/sumsq -> fused scale/shift ----------------
__global__ __launch_bounds__(256) void bn_stats_kernel(const float* __restrict__ gamma,
                                                       const float* __restrict__ beta,
                                                       int stage) {
    const int c = blockIdx.x;
    const float* z = g_bufP + c * HW;
    float s = 0.0f, q = 0.0f;
    for (int t = threadIdx.x; t < HW; t += 256) {
        float v = z[t];
        s += v;
        q = fmaf(v, v, q);
    }
    __shared__ float ssum[8], ssq[8];
    #pragma unroll
    for (int o = 16; o; o >>= 1) {
        s += __shfl_xor_sync(0xffffffffu, s, o);
        q += __shfl_xor_sync(0xffffffffu, q, o);
    }
    int lane = threadIdx.x & 31, wid = threadIdx.x >> 5;
    if (lane == 0) { ssum[wid] = s; ssq[wid] = q; }
    __syncthreads();
    if (wid == 0) {
        s = (lane < 8) ? ssum[lane] : 0.0f;
        q = (lane < 8) ? ssq[lane] : 0.0f;
        #pragma unroll
        for (int o = 4; o; o >>= 1) {
            s += __shfl_xor_sync(0xffffffffu, s, o);
            q += __shfl_xor_sync(0xffffffffu, q, o);
        }
        if (lane == 0) {
            float mu = s / (float)HW;
            float var = q / (float)HW - mu * mu;
            float sc = gamma[c] * rsqrtf(var + 1e-5f);
            g_ss[stage * 2 * COUT + c * 2]     = sc;
            g_ss[stage * 2 * COUT + c * 2 + 1] = beta[c] - mu * sc;
        }
    }
}

// ---------------- depthwise 3x3 with fused BN+LeakyReLU on the input ----------------
// grid (64, 128), block 192
__global__ __launch_bounds__(192) void dw_act_kernel(const float* __restrict__ wdw, int stage) {
    const int c = blockIdx.y;
    const int i = blockIdx.x;
    const int j = threadIdx.x;
    const float sc = g_ss[stage * 2 * COUT + c * 2];
    const float sh = g_ss[stage * 2 * COUT + c * 2 + 1];
    const float* zp = g_bufP + c * HW;
    float acc = 0.0f;
    #pragma unroll
    for (int di = 0; di < 3; di++) {
        int ii = i + di - 1;
        if ((unsigned)ii >= (unsigned)HH) continue;
        #pragma unroll
        for (int dj = 0; dj < 3; dj++) {
            int jj = j + dj - 1;
            if ((unsigned)jj >= (unsigned)WW) continue;
            float v = fmaf(zp[ii * WW + jj], sc, sh);
            v = (v >= 0.0f) ? v : 0.01f * v;
            acc = fmaf(__ldg(wdw + c * 9 + di * 3 + dj), v, acc);
        }
    }
    g_bufD[c * HW + i * WW + j] = acc;
}

// ---------------- final BN+LeakyReLU -> d_out ----------------
__global__ __launch_bounds__(256) void final_act_kernel(float* __restrict__ out) {
    const int c = blockIdx.y;
    const int t = blockIdx.x * 256 + threadIdx.x;   // 0..12287
    const float sc = g_ss[2 * 2 * COUT + c * 2];
    const float sh = g_ss[2 * 2 * COUT + c * 2 + 1];
    float v = fmaf(g_bufP[c * HW + t], sc, sh);
    v = (v >= 0.0f) ? v : 0.01f * v;
    out[c * HW + t] = v;
}

// ---------------- launch ----------------
extern "C" void kernel_launch(void* const* d_in, const int* in_sizes, int n_in,
                              void* d_out, int out_size) {
    const float* x      = (const float*)d_in[0];
    const float* xr     = (const float*)d_in[1];
    const float* rout   = (const float*)d_in[2];
    const float* wred   = (const float*)d_in[3];
    const float* g_r    = (const float*)d_in[4];
    const float* b_r    = (const float*)d_in[5];
    const float* dw1    = (const float*)d_in[6];
    const float* pw1    = (const float*)d_in[7];
    const float* g1     = (const float*)d_in[8];
    const float* b1     = (const float*)d_in[9];
    const float* dw2    = (const float*)d_in[10];
    const float* pw2    = (const float*)d_in[11];
    const float* g2     = (const float*)d_in[12];
    const float* b2     = (const float*)d_in[13];
    float* out = (float*)d_out;

    pad_kernel<<<(CIN * PP) / 256, 256>>>(x);
    gather_kernel<<<dim3(HH, 8), 192>>>(xr, rout);

    sgemm_kernel<CIN, true><<<HW / 64, 256>>>(wred);       // 256 -> 128 reduce
    bn_stats_kernel<<<COUT, 256>>>(g_r, b_r, 0);

    dw_act_kernel<<<dim3(HH, COUT), 192>>>(dw1, 0);
    sgemm_kernel<COUT, false><<<HW / 64, 256>>>(pw1);
    bn_stats_kernel<<<COUT, 256>>>(g1, b1, 1);

    dw_act_kernel<<<dim3(HH, COUT), 192>>>(dw2, 1);
    sgemm_kernel<COUT, false><<<HW / 64, 256>>>(pw2);
    bn_stats_kernel<<<COUT, 256>>>(g2, b2, 2);

    final_act_kernel<<<dim3(HW / 256, COUT), 256>>>(out);
}